// round 14
// baseline (speedup 1.0000x reference)
#include <cuda_runtime.h>
#include <cuda_bf16.h>
#include <cstdint>

// Fused BN(affine) -> ReLU -> 2x2 AvgPool(stride 2) -> 1x1 Conv (channel GEMM)
// x:           [N=32, C_in=32, H=256, W=256] f32
// conv_weight: [C_in=32, C_out=16] f32 (row-major, w[c*16+d])
// bn_scale/bn_bias: [32] f32
// out:         [N=32, C_out=16, 128, 128] f32
//
// R13: R12 (best: per-thread cp.async ring depth 5, packed f32x2 GEMM,
// st.global.cs evict-first stores -> DRAM 77.7%, 6.16 TB/s) + evict-first
// L2 policy on the READ stream too: input bytes have exactly zero reuse, so
// mark cp.async loads with createpolicy.fractional.L2::evict_first. The
// cache-policy axis is the one that moved the ceiling (R12); this is its
// read-side complement.

#define C_IN  32
#define C_OUT 16
#define HIN   256
#define WIN   256
#define POUT  128
#define CSTRIDE (HIN * WIN)   // 65536
#define PIPE  5

__device__ __forceinline__ unsigned long long pack_f32x2(float lo, float hi) {
    unsigned long long r;
    asm("mov.b64 %0, {%1, %2};" : "=l"(r) : "f"(lo), "f"(hi));
    return r;
}

__device__ __forceinline__ void fma_f32x2(unsigned long long& acc,
                                          unsigned long long a,
                                          unsigned long long b) {
    asm("fma.rn.f32x2 %0, %1, %2, %0;" : "+l"(acc) : "l"(a), "l"(b));
}

__device__ __forceinline__ unsigned long long mk_evict_first_policy() {
    unsigned long long p;
    asm("createpolicy.fractional.L2::evict_first.b64 %0, 1.0;" : "=l"(p));
    return p;
}

__device__ __forceinline__ void cp16(unsigned int smem_dst, const float* gmem_src,
                                     unsigned long long policy) {
    asm volatile("cp.async.cg.shared.global.L2::cache_hint.L2::256B "
                 "[%0], [%1], 16, %2;"
                 :: "r"(smem_dst), "l"(gmem_src), "l"(policy));
}

__device__ __forceinline__ void cp_commit() {
    asm volatile("cp.async.commit_group;");
}

template <int N>
__device__ __forceinline__ void cp_wait() {
    asm volatile("cp.async.wait_group %0;" :: "n"(N));
}

__device__ __forceinline__ unsigned int smem_u32(const void* p) {
    unsigned int a;
    asm("{ .reg .u64 t; cvta.to.shared.u64 t, %1; cvt.u32.u64 %0, t; }"
        : "=r"(a) : "l"(p));
    return a;
}

__device__ __forceinline__ void stg_cs_v2(float* p, unsigned long long v) {
    asm volatile("st.global.cs.v2.f32 [%0], {%1, %2};"
                 :: "l"(p),
                    "f"(__uint_as_float((unsigned int)(v & 0xffffffffu))),
                    "f"(__uint_as_float((unsigned int)(v >> 32)))
                 : "memory");
}

__global__ __launch_bounds__(256, 4) void fused_bn_relu_pool_conv(
    const float* __restrict__ x,
    const float* __restrict__ wmat,
    const float* __restrict__ scale,
    const float* __restrict__ bias,
    float* __restrict__ out)
{
    // Per-thread staging ring: stage[k][r][tid] (r = row 0/1 of the 2x2 window)
    __shared__ float4 stage[PIPE][2][256];              // 40 KB
    __shared__ float2 s_w2[C_IN * C_OUT];               // {0.25w, 0.25w}, 4 KB
    __shared__ float  s_sc[C_IN];
    __shared__ float  s_bi[C_IN];

    const int tid = threadIdx.x;
    for (int i = tid; i < C_IN * C_OUT; i += 256) {
        const float w = 0.25f * wmat[i];
        s_w2[i] = make_float2(w, w);
    }
    if (tid < C_IN) { s_sc[tid] = scale[tid]; s_bi[tid] = bias[tid]; }
    __syncthreads();

    const unsigned long long pol = mk_evict_first_policy();

    // Thread mapping: image n, pooled row h2, pooled columns {2*wq, 2*wq+1}
    const int g   = blockIdx.x * 256 + tid;
    const int n   = g >> 13;          // 8192 thread-slots per image
    const int rem = g & 8191;
    const int h2  = rem >> 6;         // 0..127
    const int wq  = rem & 63;         // 0..63

    const float* base = x + ((size_t)n * C_IN * HIN + 2 * h2) * WIN + 4 * wq;

    // smem addresses for this thread's ring slots; slot (k,r) at st0+(k*2+r)*4096
    const unsigned int st0 = smem_u32(&stage[0][0][tid]);

    // Prime PIPE-1 channel groups
#pragma unroll
    for (int k = 0; k < PIPE - 1; k++) {
        cp16(st0 + (unsigned int)(k * 2 + 0) * 4096u, base + (size_t)k * CSTRIDE, pol);
        cp16(st0 + (unsigned int)(k * 2 + 1) * 4096u, base + (size_t)k * CSTRIDE + WIN, pol);
        cp_commit();
    }

    unsigned long long acc[C_OUT];
#pragma unroll
    for (int d = 0; d < C_OUT; d++) acc[d] = 0ULL;

#pragma unroll
    for (int c = 0; c < C_IN; c++) {
        // Issue the load PIPE-1 channels ahead, then wait for channel c.
        if (c + PIPE - 1 < C_IN) {
            const int ck = c + PIPE - 1;
            const int k  = ck % PIPE;
            cp16(st0 + (unsigned int)(k * 2 + 0) * 4096u, base + (size_t)ck * CSTRIDE, pol);
            cp16(st0 + (unsigned int)(k * 2 + 1) * 4096u, base + (size_t)ck * CSTRIDE + WIN, pol);
            cp_commit();
            cp_wait<PIPE - 1>();   // channels <= c complete (FIFO)
        } else {
            switch (C_IN - 1 - c) {
                case 3: cp_wait<3>(); break;
                case 2: cp_wait<2>(); break;
                case 1: cp_wait<1>(); break;
                default: cp_wait<0>(); break;
            }
        }

        const int k = c % PIPE;
        const float4 r0 = stage[k][0][tid];
        const float4 r1 = stage[k][1][tid];
        const float sc = s_sc[c];
        const float bi = s_bi[c];

        // BN + ReLU on all 8 taps
        const float v0 = fmaxf(fmaf(r0.x, sc, bi), 0.0f);
        const float v1 = fmaxf(fmaf(r0.y, sc, bi), 0.0f);
        const float v2 = fmaxf(fmaf(r0.z, sc, bi), 0.0f);
        const float v3 = fmaxf(fmaf(r0.w, sc, bi), 0.0f);
        const float u0 = fmaxf(fmaf(r1.x, sc, bi), 0.0f);
        const float u1 = fmaxf(fmaf(r1.y, sc, bi), 0.0f);
        const float u2 = fmaxf(fmaf(r1.z, sc, bi), 0.0f);
        const float u3 = fmaxf(fmaf(r1.w, sc, bi), 0.0f);

        // 2x2 pool sums (the *0.25 is folded into the weights)
        const float p0 = (v0 + v1) + (u0 + u1);
        const float p1 = (v2 + v3) + (u2 + u3);
        const unsigned long long p = pack_f32x2(p0, p1);

        const unsigned long long* w2 =
            reinterpret_cast<const unsigned long long*>(&s_w2[c * C_OUT]);
#pragma unroll
        for (int d = 0; d < C_OUT; d++) {
            fma_f32x2(acc[d], p, w2[d]);
        }
    }

    // Output: out[n][d][h2][2*wq .. 2*wq+1]; acc bits are exactly {p0,p1}.
    // Streaming (evict-first) stores: output is never re-read here.
    float* o = out + (size_t)n * C_OUT * (POUT * POUT) + h2 * POUT + 2 * wq;
#pragma unroll
    for (int d = 0; d < C_OUT; d++) {
        stg_cs_v2(o + (size_t)d * (POUT * POUT), acc[d]);
    }
}

extern "C" void kernel_launch(void* const* d_in, const int* in_sizes, int n_in,
                              void* d_out, int out_size)
{
    const float* x     = (const float*)d_in[0];
    const float* wmat  = (const float*)d_in[1];
    const float* scale = (const float*)d_in[2];
    const float* bias  = (const float*)d_in[3];
    float* out         = (float*)d_out;

    // 32 images * 128 pooled rows * 64 column-pairs = 262144 threads
    fused_bn_relu_pool_conv<<<1024, 256>>>(x, wmat, scale, bias, out);
}

// round 15
// speedup vs baseline: 1.0012x; 1.0012x over previous
#include <cuda_runtime.h>
#include <cuda_bf16.h>
#include <cstdint>

// Fused BN(affine) -> ReLU -> 2x2 AvgPool(stride 2) -> 1x1 Conv (channel GEMM)
// x:           [N=32, C_in=32, H=256, W=256] f32
// conv_weight: [C_in=32, C_out=16] f32 (row-major, w[c*16+d])
// bn_scale/bn_bias: [32] f32
// out:         [N=32, C_out=16, 128, 128] f32
//
// FINAL (R12 winner, re-confirmed): per-thread cp.async ring depth 5 with
// default L2 policy + 256B promotion on the read stream (cross-warp sector
// reuse makes default policy right for reads), packed f32x2 channel GEMM,
// st.global.cs evict-first stores (zero forward reuse makes evict-first
// right for writes). 47.2us kernel / 6.16 TB/s = 77.7% of 8TB/s spec at the
// theoretical-minimum 288 MiB of traffic. 14-round ledger: occupancy, wave
// fill, request size, DMA engines, and write batching all failed to move the
// ceiling; the write-side L2 policy was the one real lever.

#define C_IN  32
#define C_OUT 16
#define HIN   256
#define WIN   256
#define POUT  128
#define CSTRIDE (HIN * WIN)   // 65536
#define PIPE  5

__device__ __forceinline__ unsigned long long pack_f32x2(float lo, float hi) {
    unsigned long long r;
    asm("mov.b64 %0, {%1, %2};" : "=l"(r) : "f"(lo), "f"(hi));
    return r;
}

__device__ __forceinline__ void fma_f32x2(unsigned long long& acc,
                                          unsigned long long a,
                                          unsigned long long b) {
    asm("fma.rn.f32x2 %0, %1, %2, %0;" : "+l"(acc) : "l"(a), "l"(b));
}

__device__ __forceinline__ void cp16(unsigned int smem_dst, const float* gmem_src) {
    asm volatile("cp.async.cg.shared.global.L2::256B [%0], [%1], 16;"
                 :: "r"(smem_dst), "l"(gmem_src));
}

__device__ __forceinline__ void cp_commit() {
    asm volatile("cp.async.commit_group;");
}

template <int N>
__device__ __forceinline__ void cp_wait() {
    asm volatile("cp.async.wait_group %0;" :: "n"(N));
}

__device__ __forceinline__ unsigned int smem_u32(const void* p) {
    unsigned int a;
    asm("{ .reg .u64 t; cvta.to.shared.u64 t, %1; cvt.u32.u64 %0, t; }"
        : "=r"(a) : "l"(p));
    return a;
}

__device__ __forceinline__ void stg_cs_v2(float* p, unsigned long long v) {
    asm volatile("st.global.cs.v2.f32 [%0], {%1, %2};"
                 :: "l"(p),
                    "f"(__uint_as_float((unsigned int)(v & 0xffffffffu))),
                    "f"(__uint_as_float((unsigned int)(v >> 32)))
                 : "memory");
}

__global__ __launch_bounds__(256, 4) void fused_bn_relu_pool_conv(
    const float* __restrict__ x,
    const float* __restrict__ wmat,
    const float* __restrict__ scale,
    const float* __restrict__ bias,
    float* __restrict__ out)
{
    // Per-thread staging ring: stage[k][r][tid] (r = row 0/1 of the 2x2 window)
    __shared__ float4 stage[PIPE][2][256];              // 40 KB
    __shared__ float2 s_w2[C_IN * C_OUT];               // {0.25w, 0.25w}, 4 KB
    __shared__ float  s_sc[C_IN];
    __shared__ float  s_bi[C_IN];

    const int tid = threadIdx.x;
    for (int i = tid; i < C_IN * C_OUT; i += 256) {
        const float w = 0.25f * wmat[i];
        s_w2[i] = make_float2(w, w);
    }
    if (tid < C_IN) { s_sc[tid] = scale[tid]; s_bi[tid] = bias[tid]; }
    __syncthreads();

    // Thread mapping: image n, pooled row h2, pooled columns {2*wq, 2*wq+1}
    const int g   = blockIdx.x * 256 + tid;
    const int n   = g >> 13;          // 8192 thread-slots per image
    const int rem = g & 8191;
    const int h2  = rem >> 6;         // 0..127
    const int wq  = rem & 63;         // 0..63

    const float* base = x + ((size_t)n * C_IN * HIN + 2 * h2) * WIN + 4 * wq;

    // smem addresses for this thread's ring slots; slot (k,r) at st0+(k*2+r)*4096
    const unsigned int st0 = smem_u32(&stage[0][0][tid]);

    // Prime PIPE-1 channel groups
#pragma unroll
    for (int k = 0; k < PIPE - 1; k++) {
        cp16(st0 + (unsigned int)(k * 2 + 0) * 4096u, base + (size_t)k * CSTRIDE);
        cp16(st0 + (unsigned int)(k * 2 + 1) * 4096u, base + (size_t)k * CSTRIDE + WIN);
        cp_commit();
    }

    unsigned long long acc[C_OUT];
#pragma unroll
    for (int d = 0; d < C_OUT; d++) acc[d] = 0ULL;

#pragma unroll
    for (int c = 0; c < C_IN; c++) {
        // Issue the load PIPE-1 channels ahead, then wait for channel c.
        if (c + PIPE - 1 < C_IN) {
            const int ck = c + PIPE - 1;
            const int k  = ck % PIPE;
            cp16(st0 + (unsigned int)(k * 2 + 0) * 4096u, base + (size_t)ck * CSTRIDE);
            cp16(st0 + (unsigned int)(k * 2 + 1) * 4096u, base + (size_t)ck * CSTRIDE + WIN);
            cp_commit();
            cp_wait<PIPE - 1>();   // channels <= c complete (FIFO)
        } else {
            switch (C_IN - 1 - c) {
                case 3: cp_wait<3>(); break;
                case 2: cp_wait<2>(); break;
                case 1: cp_wait<1>(); break;
                default: cp_wait<0>(); break;
            }
        }

        const int k = c % PIPE;
        const float4 r0 = stage[k][0][tid];
        const float4 r1 = stage[k][1][tid];
        const float sc = s_sc[c];
        const float bi = s_bi[c];

        // BN + ReLU on all 8 taps
        const float v0 = fmaxf(fmaf(r0.x, sc, bi), 0.0f);
        const float v1 = fmaxf(fmaf(r0.y, sc, bi), 0.0f);
        const float v2 = fmaxf(fmaf(r0.z, sc, bi), 0.0f);
        const float v3 = fmaxf(fmaf(r0.w, sc, bi), 0.0f);
        const float u0 = fmaxf(fmaf(r1.x, sc, bi), 0.0f);
        const float u1 = fmaxf(fmaf(r1.y, sc, bi), 0.0f);
        const float u2 = fmaxf(fmaf(r1.z, sc, bi), 0.0f);
        const float u3 = fmaxf(fmaf(r1.w, sc, bi), 0.0f);

        // 2x2 pool sums (the *0.25 is folded into the weights)
        const float p0 = (v0 + v1) + (u0 + u1);
        const float p1 = (v2 + v3) + (u2 + u3);
        const unsigned long long p = pack_f32x2(p0, p1);

        const unsigned long long* w2 =
            reinterpret_cast<const unsigned long long*>(&s_w2[c * C_OUT]);
#pragma unroll
        for (int d = 0; d < C_OUT; d++) {
            fma_f32x2(acc[d], p, w2[d]);
        }
    }

    // Output: out[n][d][h2][2*wq .. 2*wq+1]; acc bits are exactly {p0,p1}.
    // Streaming (evict-first) stores: output is never re-read by this kernel.
    float* o = out + (size_t)n * C_OUT * (POUT * POUT) + h2 * POUT + 2 * wq;
#pragma unroll
    for (int d = 0; d < C_OUT; d++) {
        stg_cs_v2(o + (size_t)d * (POUT * POUT), acc[d]);
    }
}

extern "C" void kernel_launch(void* const* d_in, const int* in_sizes, int n_in,
                              void* d_out, int out_size)
{
    const float* x     = (const float*)d_in[0];
    const float* wmat  = (const float*)d_in[1];
    const float* scale = (const float*)d_in[2];
    const float* bias  = (const float*)d_in[3];
    float* out         = (float*)d_out;

    // 32 images * 128 pooled rows * 64 column-pairs = 262144 threads
    fused_bn_relu_pool_conv<<<1024, 256>>>(x, wmat, scale, bias, out);
}

// round 16
// speedup vs baseline: 1.0018x; 1.0006x over previous
#include <cuda_runtime.h>
#include <cuda_bf16.h>
#include <cstdint>

// Fused BN(affine) -> ReLU -> 2x2 AvgPool(stride 2) -> 1x1 Conv (channel GEMM)
// x:           [N=32, C_in=32, H=256, W=256] f32
// conv_weight: [C_in=32, C_out=16] f32 (row-major, w[c*16+d])
// bn_scale/bn_bias: [32] f32
// out:         [N=32, C_out=16, 128, 128] f32
//
// R15: R12 winner (per-thread cp.async ring, packed f32x2 GEMM, st.global.cs
// evict-first stores; 47.4us / 6.13-6.16 TB/s reproduced twice) with ring
// depth 5 -> 4. Carveout trend from the PIPE sweep: smem 54KB/block was
// slightly worse than 45KB (L1D = 228KB - smem; the STG and cp.async paths
// transit L1 sectors). PIPE 4 = 36.25KB/block -> 145KB smem/SM, 83KB L1,
// still 3 channel-groups (96KB/SM) in flight -- far above the latency-
// coverage floor.

#define C_IN  32
#define C_OUT 16
#define HIN   256
#define WIN   256
#define POUT  128
#define CSTRIDE (HIN * WIN)   // 65536
#define PIPE  4

__device__ __forceinline__ unsigned long long pack_f32x2(float lo, float hi) {
    unsigned long long r;
    asm("mov.b64 %0, {%1, %2};" : "=l"(r) : "f"(lo), "f"(hi));
    return r;
}

__device__ __forceinline__ void fma_f32x2(unsigned long long& acc,
                                          unsigned long long a,
                                          unsigned long long b) {
    asm("fma.rn.f32x2 %0, %1, %2, %0;" : "+l"(acc) : "l"(a), "l"(b));
}

__device__ __forceinline__ void cp16(unsigned int smem_dst, const float* gmem_src) {
    asm volatile("cp.async.cg.shared.global.L2::256B [%0], [%1], 16;"
                 :: "r"(smem_dst), "l"(gmem_src));
}

__device__ __forceinline__ void cp_commit() {
    asm volatile("cp.async.commit_group;");
}

template <int N>
__device__ __forceinline__ void cp_wait() {
    asm volatile("cp.async.wait_group %0;" :: "n"(N));
}

__device__ __forceinline__ unsigned int smem_u32(const void* p) {
    unsigned int a;
    asm("{ .reg .u64 t; cvta.to.shared.u64 t, %1; cvt.u32.u64 %0, t; }"
        : "=r"(a) : "l"(p));
    return a;
}

__device__ __forceinline__ void stg_cs_v2(float* p, unsigned long long v) {
    asm volatile("st.global.cs.v2.f32 [%0], {%1, %2};"
                 :: "l"(p),
                    "f"(__uint_as_float((unsigned int)(v & 0xffffffffu))),
                    "f"(__uint_as_float((unsigned int)(v >> 32)))
                 : "memory");
}

__global__ __launch_bounds__(256, 4) void fused_bn_relu_pool_conv(
    const float* __restrict__ x,
    const float* __restrict__ wmat,
    const float* __restrict__ scale,
    const float* __restrict__ bias,
    float* __restrict__ out)
{
    // Per-thread staging ring: stage[k][r][tid] (r = row 0/1 of the 2x2 window)
    __shared__ float4 stage[PIPE][2][256];              // 32 KB
    __shared__ float2 s_w2[C_IN * C_OUT];               // {0.25w, 0.25w}, 4 KB
    __shared__ float  s_sc[C_IN];
    __shared__ float  s_bi[C_IN];

    const int tid = threadIdx.x;
    for (int i = tid; i < C_IN * C_OUT; i += 256) {
        const float w = 0.25f * wmat[i];
        s_w2[i] = make_float2(w, w);
    }
    if (tid < C_IN) { s_sc[tid] = scale[tid]; s_bi[tid] = bias[tid]; }
    __syncthreads();

    // Thread mapping: image n, pooled row h2, pooled columns {2*wq, 2*wq+1}
    const int g   = blockIdx.x * 256 + tid;
    const int n   = g >> 13;          // 8192 thread-slots per image
    const int rem = g & 8191;
    const int h2  = rem >> 6;         // 0..127
    const int wq  = rem & 63;         // 0..63

    const float* base = x + ((size_t)n * C_IN * HIN + 2 * h2) * WIN + 4 * wq;

    // smem addresses for this thread's ring slots; slot (k,r) at st0+(k*2+r)*4096
    const unsigned int st0 = smem_u32(&stage[0][0][tid]);

    // Prime PIPE-1 channel groups
#pragma unroll
    for (int k = 0; k < PIPE - 1; k++) {
        cp16(st0 + (unsigned int)(k * 2 + 0) * 4096u, base + (size_t)k * CSTRIDE);
        cp16(st0 + (unsigned int)(k * 2 + 1) * 4096u, base + (size_t)k * CSTRIDE + WIN);
        cp_commit();
    }

    unsigned long long acc[C_OUT];
#pragma unroll
    for (int d = 0; d < C_OUT; d++) acc[d] = 0ULL;

#pragma unroll
    for (int c = 0; c < C_IN; c++) {
        // Issue the load PIPE-1 channels ahead, then wait for channel c.
        if (c + PIPE - 1 < C_IN) {
            const int ck = c + PIPE - 1;
            const int k  = ck % PIPE;
            cp16(st0 + (unsigned int)(k * 2 + 0) * 4096u, base + (size_t)ck * CSTRIDE);
            cp16(st0 + (unsigned int)(k * 2 + 1) * 4096u, base + (size_t)ck * CSTRIDE + WIN);
            cp_commit();
            cp_wait<PIPE - 1>();   // channels <= c complete (FIFO)
        } else {
            // Tail: pending groups are channels c+1..C_IN-1
            switch (C_IN - 1 - c) {
                case 2: cp_wait<2>(); break;
                case 1: cp_wait<1>(); break;
                default: cp_wait<0>(); break;
            }
        }

        const int k = c % PIPE;
        const float4 r0 = stage[k][0][tid];
        const float4 r1 = stage[k][1][tid];
        const float sc = s_sc[c];
        const float bi = s_bi[c];

        // BN + ReLU on all 8 taps
        const float v0 = fmaxf(fmaf(r0.x, sc, bi), 0.0f);
        const float v1 = fmaxf(fmaf(r0.y, sc, bi), 0.0f);
        const float v2 = fmaxf(fmaf(r0.z, sc, bi), 0.0f);
        const float v3 = fmaxf(fmaf(r0.w, sc, bi), 0.0f);
        const float u0 = fmaxf(fmaf(r1.x, sc, bi), 0.0f);
        const float u1 = fmaxf(fmaf(r1.y, sc, bi), 0.0f);
        const float u2 = fmaxf(fmaf(r1.z, sc, bi), 0.0f);
        const float u3 = fmaxf(fmaf(r1.w, sc, bi), 0.0f);

        // 2x2 pool sums (the *0.25 is folded into the weights)
        const float p0 = (v0 + v1) + (u0 + u1);
        const float p1 = (v2 + v3) + (u2 + u3);
        const unsigned long long p = pack_f32x2(p0, p1);

        const unsigned long long* w2 =
            reinterpret_cast<const unsigned long long*>(&s_w2[c * C_OUT]);
#pragma unroll
        for (int d = 0; d < C_OUT; d++) {
            fma_f32x2(acc[d], p, w2[d]);
        }
    }

    // Output: out[n][d][h2][2*wq .. 2*wq+1]; acc bits are exactly {p0,p1}.
    // Streaming (evict-first) stores: output is never re-read by this kernel.
    float* o = out + (size_t)n * C_OUT * (POUT * POUT) + h2 * POUT + 2 * wq;
#pragma unroll
    for (int d = 0; d < C_OUT; d++) {
        stg_cs_v2(o + (size_t)d * (POUT * POUT), acc[d]);
    }
}

extern "C" void kernel_launch(void* const* d_in, const int* in_sizes, int n_in,
                              void* d_out, int out_size)
{
    const float* x     = (const float*)d_in[0];
    const float* wmat  = (const float*)d_in[1];
    const float* scale = (const float*)d_in[2];
    const float* bias  = (const float*)d_in[3];
    float* out         = (float*)d_out;

    // 32 images * 128 pooled rows * 64 column-pairs = 262144 threads
    fused_bn_relu_pool_conv<<<1024, 256>>>(x, wmat, scale, bias, out);
}